// round 14
// baseline (speedup 1.0000x reference)
#include <cuda_runtime.h>
#include <cstdint>

#define FULL_MASK 0xFFFFFFFFu

static constexpr float EPS = 1e-10f;
static constexpr float FAR_DELTA = 1e10f;
static constexpr int P = 128;           // samples per ray
static constexpr int C = 3;             // channels
static constexpr int WARPS_PER_BLOCK = 4;   // 128-thread blocks (best measured)

// One warp per ray. Each lane owns 4 consecutive samples.
// 5 independent streaming LDG.128 per lane, one warp product-scan,
// register-only feature dot products (fixed channel permutation).
__global__ __launch_bounds__(128) void volume_render_kernel(
    const float* __restrict__ density,       // [N, P]
    const float* __restrict__ feature,       // [N, P, 3]
    const float* __restrict__ depth_values,  // [N, P]
    float* __restrict__ out,                 // [N*3 feat | N depth]
    int N)
{
    const int warp = threadIdx.x >> 5;
    const int lane = threadIdx.x & 31;
    const int ray  = blockIdx.x * WARPS_PER_BLOCK + warp;
    if (ray >= N) return;

    const float4* dens4 = (const float4*)(density      + (size_t)ray * P);
    const float4* dep4  = (const float4*)(depth_values + (size_t)ray * P);
    // lane's 4 samples' features: 12 consecutive floats at lane*12
    const float4* featL = (const float4*)(feature + (size_t)ray * P * C) + lane * 3;

    // ---- front-batched independent wide streaming loads (5 x LDG.128.CS) ----
    const float4 d4 = __ldcs(&dens4[lane]);
    const float4 z4 = __ldcs(&dep4[lane]);
    const float4 fA = __ldcs(&featL[0]);   // s0.r s0.g s0.b s1.r
    const float4 fB = __ldcs(&featL[1]);   // s1.g s1.b s2.r s2.g
    const float4 fC = __ldcs(&featL[2]);   // s2.b s3.r s3.g s3.b

    // ---- deltas ----
    const float znext = __shfl_down_sync(FULL_MASK, z4.x, 1);  // z[(lane+1)*4]
    const float dl0 = z4.y - z4.x;
    const float dl1 = z4.z - z4.y;
    const float dl2 = z4.w - z4.z;
    const float dl3 = (lane == 31) ? FAR_DELTA : (znext - z4.w);

    // ---- alpha / cumprod factors ----
    const float e0 = __expf(-fmaxf(d4.x, 0.0f) * dl0);
    const float e1 = __expf(-fmaxf(d4.y, 0.0f) * dl1);
    const float e2 = __expf(-fmaxf(d4.z, 0.0f) * dl2);
    const float e3 = __expf(-fmaxf(d4.w, 0.0f) * dl3);
    const float f0 = e0 + EPS, a0 = 1.0f - e0;
    const float f1 = e1 + EPS, a1 = 1.0f - e1;
    const float f2 = e2 + EPS, a2 = 1.0f - e2;
    const float f3 = e3 + EPS, a3 = 1.0f - e3;

    // per-lane exclusive prefix products
    const float pre1 = f0;
    const float pre2 = f0 * f1;
    const float pre3 = pre2 * f2;
    const float ltot = pre3 * f3;

    // ---- warp inclusive product scan over lane totals ----
    float v = ltot;
    #pragma unroll
    for (int off = 1; off < 32; off <<= 1) {
        const float t = __shfl_up_sync(FULL_MASK, v, off);
        if (lane >= off) v *= t;
    }
    float Lex = __shfl_up_sync(FULL_MASK, v, 1);  // product of preceding lanes
    if (lane == 0) Lex = 1.0f;

    // ---- weights ----
    const float w0 = Lex * a0;
    const float w1 = Lex * pre1 * a1;
    const float w2 = Lex * pre2 * a2;
    const float w3 = Lex * pre3 * a3;

    // ---- register-only accumulation (fixed permutation) ----
    float acc_r = w0 * fA.x + w1 * fA.w + w2 * fB.z + w3 * fC.y;
    float acc_g = w0 * fA.y + w1 * fB.x + w2 * fB.w + w3 * fC.z;
    float acc_b = w0 * fA.z + w1 * fB.y + w2 * fC.x + w3 * fC.w;
    float acc_d = w0 * z4.x + w1 * z4.y + w2 * z4.z + w3 * z4.w;

    // ---- warp butterfly reduction: every lane ends with the full sums ----
    #pragma unroll
    for (int off = 16; off > 0; off >>= 1) {
        acc_r += __shfl_xor_sync(FULL_MASK, acc_r, off);
        acc_g += __shfl_xor_sync(FULL_MASK, acc_g, off);
        acc_b += __shfl_xor_sync(FULL_MASK, acc_b, off);
        acc_d += __shfl_xor_sync(FULL_MASK, acc_d, off);
    }

    // spread the 4 output stores across lanes 0..3 (all hold the sums)
    if (lane < 4) {
        float* feat_out  = out;                   // [N, 3]
        float* depth_out = out + (size_t)N * C;   // [N]
        const float vals[4] = {acc_r, acc_g, acc_b, acc_d};
        if (lane == 3) {
            __stcs(&depth_out[ray], vals[3]);
        } else {
            __stcs(&feat_out[(size_t)ray * C + lane], vals[lane]);
        }
    }
}

extern "C" void kernel_launch(void* const* d_in, const int* in_sizes, int n_in,
                              void* d_out, int out_size)
{
    const float* density      = (const float*)d_in[0];
    const float* feature      = (const float*)d_in[1];
    const float* depth_values = (const float*)d_in[2];
    float* out = (float*)d_out;

    const int N = in_sizes[0] / P;   // density is [N, P]

    const int blocks = (N + WARPS_PER_BLOCK - 1) / WARPS_PER_BLOCK;
    volume_render_kernel<<<blocks, 128>>>(density, feature, depth_values, out, N);
}

// round 15
// speedup vs baseline: 1.0094x; 1.0094x over previous
#include <cuda_runtime.h>
#include <cstdint>

#define FULL_MASK 0xFFFFFFFFu

static constexpr float EPS = 1e-10f;
static constexpr float FAR_DELTA = 1e10f;
static constexpr int P = 128;           // samples per ray
static constexpr int C = 3;             // channels
static constexpr int WARPS_PER_BLOCK = 4;   // 128-thread blocks (best measured)

// One warp per ray. Each lane owns 4 consecutive samples.
// 5 independent streaming LDG.128 per lane, one warp product-scan,
// register-only feature dot products (fixed channel permutation).
__global__ __launch_bounds__(128) void volume_render_kernel(
    const float* __restrict__ density,       // [N, P]
    const float* __restrict__ feature,       // [N, P, 3]
    const float* __restrict__ depth_values,  // [N, P]
    float* __restrict__ out,                 // [N*3 feat | N depth]
    int N)
{
    const int warp = threadIdx.x >> 5;
    const int lane = threadIdx.x & 31;
    const int ray  = blockIdx.x * WARPS_PER_BLOCK + warp;
    if (ray >= N) return;

    const float4* dens4 = (const float4*)(density      + (size_t)ray * P);
    const float4* dep4  = (const float4*)(depth_values + (size_t)ray * P);
    // lane's 4 samples' features: 12 consecutive floats at lane*12
    const float4* featL = (const float4*)(feature + (size_t)ray * P * C) + lane * 3;

    // ---- front-batched independent wide streaming loads (5 x LDG.128.CS) ----
    const float4 d4 = __ldcs(&dens4[lane]);
    const float4 z4 = __ldcs(&dep4[lane]);
    const float4 fA = __ldcs(&featL[0]);   // s0.r s0.g s0.b s1.r
    const float4 fB = __ldcs(&featL[1]);   // s1.g s1.b s2.r s2.g
    const float4 fC = __ldcs(&featL[2]);   // s2.b s3.r s3.g s3.b

    // ---- deltas ----
    const float znext = __shfl_down_sync(FULL_MASK, z4.x, 1);  // z[(lane+1)*4]
    const float dl0 = z4.y - z4.x;
    const float dl1 = z4.z - z4.y;
    const float dl2 = z4.w - z4.z;
    const float dl3 = (lane == 31) ? FAR_DELTA : (znext - z4.w);

    // ---- alpha / cumprod factors ----
    const float e0 = __expf(-fmaxf(d4.x, 0.0f) * dl0);
    const float e1 = __expf(-fmaxf(d4.y, 0.0f) * dl1);
    const float e2 = __expf(-fmaxf(d4.z, 0.0f) * dl2);
    const float e3 = __expf(-fmaxf(d4.w, 0.0f) * dl3);
    const float f0 = e0 + EPS, a0 = 1.0f - e0;
    const float f1 = e1 + EPS, a1 = 1.0f - e1;
    const float f2 = e2 + EPS, a2 = 1.0f - e2;
    const float f3 = e3 + EPS, a3 = 1.0f - e3;

    // per-lane exclusive prefix products
    const float pre1 = f0;
    const float pre2 = f0 * f1;
    const float pre3 = pre2 * f2;
    const float ltot = pre3 * f3;

    // ---- warp inclusive product scan over lane totals ----
    float v = ltot;
    #pragma unroll
    for (int off = 1; off < 32; off <<= 1) {
        const float t = __shfl_up_sync(FULL_MASK, v, off);
        if (lane >= off) v *= t;
    }
    float Lex = __shfl_up_sync(FULL_MASK, v, 1);  // product of preceding lanes
    if (lane == 0) Lex = 1.0f;

    // ---- weights ----
    const float w0 = Lex * a0;
    const float w1 = Lex * pre1 * a1;
    const float w2 = Lex * pre2 * a2;
    const float w3 = Lex * pre3 * a3;

    // ---- register-only accumulation (fixed permutation) ----
    float acc_r = w0 * fA.x + w1 * fA.w + w2 * fB.z + w3 * fC.y;
    float acc_g = w0 * fA.y + w1 * fB.x + w2 * fB.w + w3 * fC.z;
    float acc_b = w0 * fA.z + w1 * fB.y + w2 * fC.x + w3 * fC.w;
    float acc_d = w0 * z4.x + w1 * z4.y + w2 * z4.z + w3 * z4.w;

    // ---- warp butterfly reduction: every lane ends with the full sums ----
    #pragma unroll
    for (int off = 16; off > 0; off >>= 1) {
        acc_r += __shfl_xor_sync(FULL_MASK, acc_r, off);
        acc_g += __shfl_xor_sync(FULL_MASK, acc_g, off);
        acc_b += __shfl_xor_sync(FULL_MASK, acc_b, off);
        acc_d += __shfl_xor_sync(FULL_MASK, acc_d, off);
    }

    // spread the 4 output stores across lanes 0..3 (all hold the sums)
    if (lane < 4) {
        float* feat_out  = out;                   // [N, 3]
        float* depth_out = out + (size_t)N * C;   // [N]
        const float vals[4] = {acc_r, acc_g, acc_b, acc_d};
        if (lane == 3) {
            __stcs(&depth_out[ray], vals[3]);
        } else {
            __stcs(&feat_out[(size_t)ray * C + lane], vals[lane]);
        }
    }
}

extern "C" void kernel_launch(void* const* d_in, const int* in_sizes, int n_in,
                              void* d_out, int out_size)
{
    const float* density      = (const float*)d_in[0];
    const float* feature      = (const float*)d_in[1];
    const float* depth_values = (const float*)d_in[2];
    float* out = (float*)d_out;

    const int N = in_sizes[0] / P;   // density is [N, P]

    const int blocks = (N + WARPS_PER_BLOCK - 1) / WARPS_PER_BLOCK;
    volume_render_kernel<<<blocks, 128>>>(density, feature, depth_values, out, N);
}